// round 1
// baseline (speedup 1.0000x reference)
#include <cuda_runtime.h>
#include <cstdint>

#define CCLS 8192
#define BSZ  512
#define HH   8
#define RG   8                     // rows (b) per product group
#define THREADS 256
#define C4   (CCLS/4)              // 2048 float4-columns
#define NRG  (BSZ/RG)              // 64 row groups
#define MAIN_BLOCKS ((C4*NRG)/THREADS)  // 512

__device__ float g_w[CCLS];
__device__ float g_part[MAIN_BLOCKS];

// w[c] = sum_h lam[h] * La[h][c]
__global__ void k_weights(const float* __restrict__ La, const float* __restrict__ lam) {
    int c = blockIdx.x * blockDim.x + threadIdx.x;
    float acc = 0.f;
#pragma unroll
    for (int h = 0; h < HH; h++)
        acc = fmaf(lam[h], La[h * CCLS + c], acc);
    g_w[c] = acc;
}

__device__ __forceinline__ unsigned long long pack2(unsigned a, unsigned b) {
    unsigned long long r;
    asm("mov.b64 %0, {%1, %2};" : "=l"(r) : "r"(a), "r"(b));
    return r;
}

__device__ __forceinline__ void unpack2(unsigned long long v, unsigned& a, unsigned& b) {
    asm("mov.b64 {%0, %1}, %2;" : "=r"(a), "=r"(b) : "l"(v));
}

__device__ __forceinline__ unsigned long long fma2(unsigned long long a,
                                                   unsigned long long b,
                                                   unsigned long long c) {
    unsigned long long d;
    asm("fma.rn.f32x2 %0, %1, %2, %3;" : "=l"(d) : "l"(a), "l"(b), "l"(c));
    return d;
}

// Each thread: 4 consecutive columns (one float4) x 8 consecutive batch rows.
// prod_c = PROD_{r in group} (1 - |p - yt|);  contribution = max(log2 prod, CL2) * w[c]
__global__ void __launch_bounds__(THREADS)
k_main(const float* __restrict__ yp, const float* __restrict__ yt) {
    int unit = blockIdx.x * THREADS + threadIdx.x;
    int c4 = unit & (C4 - 1);
    int rg = unit >> 11;                      // log2(C4) = 11
    size_t base = (size_t)rg * RG * C4 + c4;  // in float4 units
    const uint4* P = (const uint4*)yp + base;
    const uint4* T = (const uint4*)yt + base;

    const unsigned long long NEG1 = 0xBF800000BF800000ull; // {-1.f,-1.f}
    const unsigned long long SGN  = 0x8000000080000000ull;
    unsigned long long prod01 = 0x3F8000003F800000ull;     // {1.f,1.f}
    unsigned long long prod23 = 0x3F8000003F800000ull;

#pragma unroll
    for (int r = 0; r < RG; r++) {
        uint4 pv = P[(size_t)r * C4];
        uint4 tv = T[(size_t)r * C4];
        unsigned long long p01 = pack2(pv.x, pv.y);
        unsigned long long p23 = pack2(pv.z, pv.w);
        unsigned long long t01 = pack2(tv.x, tv.y);
        unsigned long long t23 = pack2(tv.z, tv.w);
        // d = p - yt   (fma(t, -1, p)), then force sign bit -> -|d|
        unsigned long long d01 = fma2(t01, NEG1, p01) | SGN;
        unsigned long long d23 = fma2(t23, NEG1, p23) | SGN;
        // prod = prod * (1 - |d|)  ==  fma(-|d|, prod, prod)
        prod01 = fma2(d01, prod01, prod01);
        prod23 = fma2(d23, prod23, prod23);
    }

    unsigned a0, a1, a2, a3;
    unpack2(prod01, a0, a1);
    unpack2(prod23, a2, a3);
    const float4 w4 = ((const float4*)g_w)[c4];
    const float CL2 = -144.26950408889634f;   // -100 / ln(2)

    float l, acc;
    l   = fmaxf(__log2f(__uint_as_float(a0)), CL2); acc = l * w4.x;
    l   = fmaxf(__log2f(__uint_as_float(a1)), CL2); acc = fmaf(l, w4.y, acc);
    l   = fmaxf(__log2f(__uint_as_float(a2)), CL2); acc = fmaf(l, w4.z, acc);
    l   = fmaxf(__log2f(__uint_as_float(a3)), CL2); acc = fmaf(l, w4.w, acc);

    // block reduction (deterministic)
#pragma unroll
    for (int o = 16; o; o >>= 1) acc += __shfl_xor_sync(0xFFFFFFFFu, acc, o);
    __shared__ float sh[THREADS / 32];
    if ((threadIdx.x & 31) == 0) sh[threadIdx.x >> 5] = acc;
    __syncthreads();
    if (threadIdx.x < THREADS / 32) {
        float v = sh[threadIdx.x];
#pragma unroll
        for (int o = (THREADS / 64); o; o >>= 1) v += __shfl_xor_sync(0xFFu, v, o);
        if (threadIdx.x == 0) g_part[blockIdx.x] = v;
    }
}

__global__ void k_final(float* __restrict__ out) {
    __shared__ float sh[MAIN_BLOCKS];
    int t = threadIdx.x;
    sh[t] = g_part[t];
    __syncthreads();
#pragma unroll
    for (int s = MAIN_BLOCKS / 2; s > 0; s >>= 1) {
        if (t < s) sh[t] += sh[t + s];
        __syncthreads();
    }
    if (t == 0) out[0] = sh[0] * (-0.69314718055994531f / (float)CCLS);
}

extern "C" void kernel_launch(void* const* d_in, const int* in_sizes, int n_in,
                              void* d_out, int out_size) {
    const float* y_pred = (const float*)d_in[0];
    const float* y_true = (const float*)d_in[1];
    const float* La     = (const float*)d_in[2];
    const float* lam    = (const float*)d_in[3];
    (void)in_sizes; (void)n_in; (void)out_size;

    k_weights<<<CCLS / 256, 256>>>(La, lam);
    k_main<<<MAIN_BLOCKS, THREADS>>>(y_pred, y_true);
    k_final<<<1, MAIN_BLOCKS>>>((float*)d_out);
}

// round 2
// speedup vs baseline: 1.0712x; 1.0712x over previous
#include <cuda_runtime.h>
#include <cstdint>

#define CCLS 8192
#define BSZ  512
#define HH   8
#define RG   8                     // rows (b) per product group
#define THREADS 256
#define C4   (CCLS/4)              // 2048 float4-columns
#define NRG  (BSZ/RG)              // 64 row groups
#define NBLK ((C4*NRG)/THREADS)    // 512 blocks

__device__ float    g_part[NBLK];
__device__ unsigned g_cnt = 0;     // wraps back to 0 every full grid -> replay-safe

__device__ __forceinline__ unsigned long long pack2(unsigned a, unsigned b) {
    unsigned long long r;
    asm("mov.b64 %0, {%1, %2};" : "=l"(r) : "r"(a), "r"(b));
    return r;
}
__device__ __forceinline__ void unpack2(unsigned long long v, unsigned& a, unsigned& b) {
    asm("mov.b64 {%0, %1}, %2;" : "=r"(a), "=r"(b) : "l"(v));
}
__device__ __forceinline__ unsigned long long fma2(unsigned long long a,
                                                   unsigned long long b,
                                                   unsigned long long c) {
    unsigned long long d;
    asm("fma.rn.f32x2 %0, %1, %2, %3;" : "=l"(d) : "l"(a), "l"(b), "l"(c));
    return d;
}

// Single fused kernel:
//   per-thread: 4 consecutive columns (one float4) x 8 consecutive batch rows
//   prod_c = PROD_r (1 - |p - yt|)   [exactly yt?p:1-p since yt binary, La fold]
//   w[c]   = sum_h lam[h]*La[h][c]   (computed inline, L2-hot)
//   contribution = max(log2 prod, -100/ln2) * w[c];  block-reduce; last block
//   sums the 512 partials and writes out.
__global__ void __launch_bounds__(THREADS)
k_fused(const float* __restrict__ yp, const float* __restrict__ yt,
        const float* __restrict__ La, const float* __restrict__ lam,
        float* __restrict__ out) {
    int unit = blockIdx.x * THREADS + threadIdx.x;
    int c4 = unit & (C4 - 1);
    int rg = unit >> 11;                      // log2(C4) = 11
    size_t base = (size_t)rg * RG * C4 + c4;  // in float4 units
    const uint4* P = (const uint4*)yp + base;
    const uint4* T = (const uint4*)yt + base;

    // --- inline weights: w4[c] = sum_h lam[h] * La[h][c] (registers only) ---
    const float4* La4 = (const float4*)La;
    float4 w4 = make_float4(0.f, 0.f, 0.f, 0.f);
#pragma unroll
    for (int h = 0; h < HH; h++) {
        float lm = __ldg(&lam[h]);
        float4 a = __ldg(&La4[(size_t)h * C4 + c4]);
        w4.x = fmaf(lm, a.x, w4.x);
        w4.y = fmaf(lm, a.y, w4.y);
        w4.z = fmaf(lm, a.z, w4.z);
        w4.w = fmaf(lm, a.w, w4.w);
    }

    // --- main product loop over 8 rows ---
    const unsigned long long NEG1 = 0xBF800000BF800000ull; // {-1.f,-1.f}
    const unsigned long long SGN  = 0x8000000080000000ull;
    unsigned long long prod01 = 0x3F8000003F800000ull;     // {1.f,1.f}
    unsigned long long prod23 = 0x3F8000003F800000ull;
#pragma unroll
    for (int r = 0; r < RG; r++) {
        uint4 pv = P[(size_t)r * C4];
        uint4 tv = T[(size_t)r * C4];
        unsigned long long p01 = pack2(pv.x, pv.y);
        unsigned long long p23 = pack2(pv.z, pv.w);
        unsigned long long t01 = pack2(tv.x, tv.y);
        unsigned long long t23 = pack2(tv.z, tv.w);
        unsigned long long d01 = fma2(t01, NEG1, p01) | SGN;  // -|p-yt|
        unsigned long long d23 = fma2(t23, NEG1, p23) | SGN;
        prod01 = fma2(d01, prod01, prod01);                   // *= (1-|d|)
        prod23 = fma2(d23, prod23, prod23);
    }

    unsigned a0, a1, a2, a3;
    unpack2(prod01, a0, a1);
    unpack2(prod23, a2, a3);
    const float CL2 = -144.26950408889634f;   // -100 / ln(2)
    float l, acc;
    l   = fmaxf(__log2f(__uint_as_float(a0)), CL2); acc = l * w4.x;
    l   = fmaxf(__log2f(__uint_as_float(a1)), CL2); acc = fmaf(l, w4.y, acc);
    l   = fmaxf(__log2f(__uint_as_float(a2)), CL2); acc = fmaf(l, w4.z, acc);
    l   = fmaxf(__log2f(__uint_as_float(a3)), CL2); acc = fmaf(l, w4.w, acc);

    // --- block reduction ---
#pragma unroll
    for (int o = 16; o; o >>= 1) acc += __shfl_xor_sync(0xFFFFFFFFu, acc, o);
    __shared__ float sh[THREADS / 32];
    if ((threadIdx.x & 31) == 0) sh[threadIdx.x >> 5] = acc;
    __syncthreads();
    if (threadIdx.x < THREADS / 32) {
        float v = sh[threadIdx.x];
#pragma unroll
        for (int o = (THREADS / 64); o; o >>= 1) v += __shfl_xor_sync(0xFFu, v, o);
        if (threadIdx.x == 0) g_part[blockIdx.x] = v;
    }

    // --- last-block final reduction (replay-safe wrap counter) ---
    __shared__ bool isLast;
    __threadfence();
    if (threadIdx.x == 0) {
        unsigned t = atomicInc(&g_cnt, NBLK - 1);
        isLast = (t == NBLK - 1);
    }
    __syncthreads();
    if (isLast) {
        float v = g_part[threadIdx.x] + g_part[threadIdx.x + THREADS];
#pragma unroll
        for (int o = 16; o; o >>= 1) v += __shfl_xor_sync(0xFFFFFFFFu, v, o);
        __shared__ float sh2[THREADS / 32];
        if ((threadIdx.x & 31) == 0) sh2[threadIdx.x >> 5] = v;
        __syncthreads();
        if (threadIdx.x < THREADS / 32) {
            float s = sh2[threadIdx.x];
#pragma unroll
            for (int o = (THREADS / 64); o; o >>= 1) s += __shfl_xor_sync(0xFFu, s, o);
            if (threadIdx.x == 0)
                out[0] = s * (-0.69314718055994531f / (float)CCLS);
        }
    }
}

extern "C" void kernel_launch(void* const* d_in, const int* in_sizes, int n_in,
                              void* d_out, int out_size) {
    const float* y_pred = (const float*)d_in[0];
    const float* y_true = (const float*)d_in[1];
    const float* La     = (const float*)d_in[2];
    const float* lam    = (const float*)d_in[3];
    (void)in_sizes; (void)n_in; (void)out_size;

    k_fused<<<NBLK, THREADS>>>(y_pred, y_true, La, lam, (float*)d_out);
}

// round 3
// speedup vs baseline: 1.0745x; 1.0031x over previous
#include <cuda_runtime.h>
#include <cstdint>

#define CCLS 8192
#define BSZ  512
#define HH   8
#define RG   8                     // rows (b) per product group
#define THREADS 256
#define C4   (CCLS/4)              // 2048 float4-columns
#define NRG  (BSZ/RG)              // 64 row groups
#define NBLK ((C4*NRG)/THREADS)    // 512 blocks

__device__ float    g_part[NBLK];
__device__ unsigned g_cnt = 0;     // wraps to 0 each full grid -> replay-safe

__device__ __forceinline__ unsigned long long pack2(unsigned a, unsigned b) {
    unsigned long long r;
    asm("mov.b64 %0, {%1, %2};" : "=l"(r) : "r"(a), "r"(b));
    return r;
}
__device__ __forceinline__ void unpack2(unsigned long long v, unsigned& a, unsigned& b) {
    asm("mov.b64 {%0, %1}, %2;" : "=r"(a), "=r"(b) : "l"(v));
}
__device__ __forceinline__ unsigned long long fma2(unsigned long long a,
                                                   unsigned long long b,
                                                   unsigned long long c) {
    unsigned long long d;
    asm("fma.rn.f32x2 %0, %1, %2, %3;" : "=l"(d) : "l"(a), "l"(b), "l"(c));
    return d;
}

// Single fused kernel. Per-thread: 4 consecutive columns x 8 consecutive rows.
//   prod_c = PROD_r (1 - |p - yt|)  (== yt?p:1-p elementwise, binary yt; La folds
//   out because masked entries contribute exactly 0 under the -100 log clamp)
//   w[c] = sum_h lam[h]*La[h][c] computed inline (L2-hot re-read)
//   result = sum w[c] * max(log2 prod, -100/ln2) * (-ln2/C)
// All 16 main LDG.128 are front-batched for MLP; launch_bounds caps regs at 64
// so occupancy stays at 4 blocks/SM while ptxas sinks loads as needed.
__global__ void __launch_bounds__(THREADS, 4)
k_fused(const float* __restrict__ yp, const float* __restrict__ yt,
        const float* __restrict__ La, const float* __restrict__ lam,
        float* __restrict__ out) {
    int unit = blockIdx.x * THREADS + threadIdx.x;
    int c4 = unit & (C4 - 1);
    int rg = unit >> 11;                      // log2(C4) = 11
    size_t base = (size_t)rg * RG * C4 + c4;  // in float4 units
    const uint4* P = (const uint4*)yp + base;
    const uint4* T = (const uint4*)yt + base;

    // ---- batch-issue the DRAM-critical stream first (16 x LDG.128) ----
    uint4 pv[RG], tv[RG];
#pragma unroll
    for (int r = 0; r < RG; r++) pv[r] = P[(size_t)r * C4];
#pragma unroll
    for (int r = 0; r < RG; r++) tv[r] = T[(size_t)r * C4];

    // ---- weights (overlaps with in-flight main loads) ----
    const float4* La4 = (const float4*)La;
    float4 lamA = ((const float4*)lam)[0];
    float4 lamB = ((const float4*)lam)[1];
    float lm[HH] = {lamA.x, lamA.y, lamA.z, lamA.w, lamB.x, lamB.y, lamB.z, lamB.w};
    float4 w4 = make_float4(0.f, 0.f, 0.f, 0.f);
#pragma unroll
    for (int h = 0; h < HH; h++) {
        float4 a = La4[(size_t)h * C4 + c4];
        w4.x = fmaf(lm[h], a.x, w4.x);
        w4.y = fmaf(lm[h], a.y, w4.y);
        w4.z = fmaf(lm[h], a.z, w4.z);
        w4.w = fmaf(lm[h], a.w, w4.w);
    }

    // ---- product over 8 rows, two independent f32x2 chains ----
    const unsigned long long NEG1 = 0xBF800000BF800000ull; // {-1.f,-1.f}
    const unsigned long long SGN  = 0x8000000080000000ull;
    unsigned long long prod01 = 0x3F8000003F800000ull;     // {1.f,1.f}
    unsigned long long prod23 = 0x3F8000003F800000ull;
#pragma unroll
    for (int r = 0; r < RG; r++) {
        unsigned long long p01 = pack2(pv[r].x, pv[r].y);
        unsigned long long p23 = pack2(pv[r].z, pv[r].w);
        unsigned long long t01 = pack2(tv[r].x, tv[r].y);
        unsigned long long t23 = pack2(tv[r].z, tv[r].w);
        unsigned long long d01 = fma2(t01, NEG1, p01) | SGN;  // -|p-yt|
        unsigned long long d23 = fma2(t23, NEG1, p23) | SGN;
        prod01 = fma2(d01, prod01, prod01);                   // *= (1-|d|)
        prod23 = fma2(d23, prod23, prod23);
    }

    unsigned a0, a1, a2, a3;
    unpack2(prod01, a0, a1);
    unpack2(prod23, a2, a3);
    const float CL2 = -144.26950408889634f;   // -100 / ln(2)
    float l, acc;
    l   = fmaxf(__log2f(__uint_as_float(a0)), CL2); acc = l * w4.x;
    l   = fmaxf(__log2f(__uint_as_float(a1)), CL2); acc = fmaf(l, w4.y, acc);
    l   = fmaxf(__log2f(__uint_as_float(a2)), CL2); acc = fmaf(l, w4.z, acc);
    l   = fmaxf(__log2f(__uint_as_float(a3)), CL2); acc = fmaf(l, w4.w, acc);

    // ---- block reduction ----
#pragma unroll
    for (int o = 16; o; o >>= 1) acc += __shfl_xor_sync(0xFFFFFFFFu, acc, o);
    __shared__ float sh[THREADS / 32];
    if ((threadIdx.x & 31) == 0) sh[threadIdx.x >> 5] = acc;
    __syncthreads();
    if (threadIdx.x < THREADS / 32) {
        float v = sh[threadIdx.x];
#pragma unroll
        for (int o = (THREADS / 64); o; o >>= 1) v += __shfl_xor_sync(0xFFu, v, o);
        if (threadIdx.x == 0) g_part[blockIdx.x] = v;
    }

    // ---- last-block final reduction ----
    __shared__ bool isLast;
    __threadfence();
    if (threadIdx.x == 0) {
        unsigned t = atomicInc(&g_cnt, NBLK - 1);
        isLast = (t == NBLK - 1);
    }
    __syncthreads();
    if (isLast) {
        float v = g_part[threadIdx.x] + g_part[threadIdx.x + THREADS];
#pragma unroll
        for (int o = 16; o; o >>= 1) v += __shfl_xor_sync(0xFFFFFFFFu, v, o);
        __shared__ float sh2[THREADS / 32];
        if ((threadIdx.x & 31) == 0) sh2[threadIdx.x >> 5] = v;
        __syncthreads();
        if (threadIdx.x < THREADS / 32) {
            float s = sh2[threadIdx.x];
#pragma unroll
            for (int o = (THREADS / 64); o; o >>= 1) s += __shfl_xor_sync(0xFFu, s, o);
            if (threadIdx.x == 0)
                out[0] = s * (-0.69314718055994531f / (float)CCLS);
        }
    }
}

extern "C" void kernel_launch(void* const* d_in, const int* in_sizes, int n_in,
                              void* d_out, int out_size) {
    const float* y_pred = (const float*)d_in[0];
    const float* y_true = (const float*)d_in[1];
    const float* La     = (const float*)d_in[2];
    const float* lam    = (const float*)d_in[3];
    (void)in_sizes; (void)n_in; (void)out_size;

    k_fused<<<NBLK, THREADS>>>(y_pred, y_true, La, lam, (float*)d_out);
}